// round 14
// baseline (speedup 1.0000x reference)
#include <cuda_runtime.h>
#include <cuda_fp16.h>
#include <cstdint>

// ============================================================================
// DQSN collapsed: out = A @ w2' + b2*(1-2^-16)
//   A[b,j] = sum_t spike_t(h_in[b,j]) * 2^(t-17),  h_in = x@w1' + b1
// GEMM1: fp16 mma, logical K-tripling [xh|xh|xl]x[wh|wl|wh] (K'=768).
//   R13 (resubmit; prior round was an infra failure): 128-thread CTAs,
//   4 warps x 64x64 warp tiles (occ 2 -> 256-reg cap). Same 8 warps/SM as
//   R10 but -33% smem fragment traffic (R10/R12 evidence: LDS bandwidth,
//   not HMMA, was binding at 64x32 tiles).
// GEMM2: single-product fp16 Ah @ wh' (K=1024), exact R10 config.
// Near-threshold IF elements (|v-1|<1e-4) recomputed in-CTA with sequential
// fp32 FMA (reference rounding). 3-product GEMM1 is mandatory: 2-product
// pushes v-err to ~2e-3 -> flagged set explodes (quantified R12 post-mortem).
// ============================================================================

#define MDIM 8192
#define IDIM 256
#define HDIM 1024
#define ODIM 256

#define G1_NK 12            // K'=768 in BK=64 tiles
#define G2_NK 16            // K=1024 in BK=64 tiles
#define STRIDE 72           // halves per smem row (144B, ldmatrix conflict-free)
#define G1_STAGE (256 * STRIDE)               // halves: 128 A + 128 B rows
#define G2_STAGE (192 * STRIDE)               // halves: 128 A + 64 W rows
#define G1_SMEM (2 * G1_STAGE * 2)            // 73728 B
#define G2_SMEM (2 * G2_STAGE * 2)            // 55296 B
#define FIX_CAP 2048
#define DELTA 1e-4f

// --------------------------- global scratch (no allocs) ---------------------
__device__ __align__(16) __half g_xh [(size_t)MDIM * IDIM];
__device__ __align__(16) __half g_xl [(size_t)MDIM * IDIM];
__device__ __align__(16) __half g_w1h[(size_t)HDIM * IDIM];
__device__ __align__(16) __half g_w1l[(size_t)HDIM * IDIM];
__device__ __align__(16) __half g_w2h[(size_t)ODIM * HDIM];
__device__ __align__(16) __half g_Ah [(size_t)MDIM * HDIM];

// --------------------------- helpers ----------------------------------------
__device__ __forceinline__ void cp16(uint32_t s, const void* g) {
    asm volatile("cp.async.cg.shared.global [%0], [%1], 16;" :: "r"(s), "l"(g));
}
#define CP_COMMIT() asm volatile("cp.async.commit_group;" ::: "memory")
#define CP_WAIT0()  asm volatile("cp.async.wait_group 0;" ::: "memory")

__device__ __forceinline__ void ldm_x4(uint32_t* r, uint32_t addr) {
    asm volatile("ldmatrix.sync.aligned.m8n8.x4.shared.b16 {%0,%1,%2,%3}, [%4];"
        : "=r"(r[0]), "=r"(r[1]), "=r"(r[2]), "=r"(r[3]) : "r"(addr));
}
__device__ __forceinline__ void mma_f16(float* c, const uint32_t* a, const uint32_t* b) {
    asm volatile(
        "mma.sync.aligned.m16n8k16.row.col.f32.f16.f16.f32 "
        "{%0,%1,%2,%3}, {%4,%5,%6,%7}, {%8,%9}, {%0,%1,%2,%3};"
        : "+f"(c[0]), "+f"(c[1]), "+f"(c[2]), "+f"(c[3])
        : "r"(a[0]), "r"(a[1]), "r"(a[2]), "r"(a[3]), "r"(b[0]), "r"(b[1]));
}
__device__ __forceinline__ uint32_t pack_h2(float a, float b) {
    __half2 t = __floats2half2_rn(a, b);
    return *reinterpret_cast<uint32_t*>(&t);
}

// IF neuron closed-form sim
__device__ __forceinline__ float if_sim(float h) {
    float v = 0.0f, av = 0.0f, coef = 0x1p-16f;
#pragma unroll
    for (int t = 0; t < 16; t++) {
        v += h;
        const bool s = (v >= 1.0f);
        av = s ? (av + coef) : av;
        v = s ? 0.0f : v;
        coef += coef;
    }
    return av;
}
__device__ __forceinline__ float if_sim_flag(float h, bool& near) {
    float v = 0.0f, av = 0.0f, coef = 0x1p-16f;
#pragma unroll
    for (int t = 0; t < 16; t++) {
        v += h;
        near |= (fabsf(v - 1.0f) < DELTA);
        const bool s = (v >= 1.0f);
        av = s ? (av + coef) : av;
        v = s ? 0.0f : v;
        coef += coef;
    }
    return av;
}

// --------------------------- fused converter (4 floats/thread) ---------------
#define CONV_Q1 (MDIM * IDIM / 4)
#define CONV_Q2 (HDIM * IDIM / 4)
#define CONV_Q3 (ODIM * HDIM / 4)
#define CONV_QTOTAL (CONV_Q1 + CONV_Q2 + CONV_Q3)

__global__ __launch_bounds__(256)
void conv_all_kernel(const float* __restrict__ x, const float* __restrict__ w1,
                     const float* __restrict__ w2,
                     __half* __restrict__ xh, __half* __restrict__ xl,
                     __half* __restrict__ w1h, __half* __restrict__ w1l,
                     __half* __restrict__ w2h)
{
    const int i = blockIdx.x * blockDim.x + threadIdx.x;   // quad index
    if (i < CONV_Q1 + CONV_Q2) {
        const float* src;
        __half *dhi, *dlo;
        int idx;
        if (i < CONV_Q1) { src = x;  dhi = xh;  dlo = xl;  idx = i; }
        else             { src = w1; dhi = w1h; dlo = w1l; idx = i - CONV_Q1; }
        const float4 v = *reinterpret_cast<const float4*>(src + (size_t)idx * 4);
        const __half h0 = __float2half_rn(v.x), h1 = __float2half_rn(v.y);
        const __half h2 = __float2half_rn(v.z), h3 = __float2half_rn(v.w);
        uint2 hu, lu;
        hu.x = pack_h2(__half2float(h0), __half2float(h1));
        hu.y = pack_h2(__half2float(h2), __half2float(h3));
        lu.x = pack_h2(v.x - __half2float(h0), v.y - __half2float(h1));
        lu.y = pack_h2(v.z - __half2float(h2), v.w - __half2float(h3));
        reinterpret_cast<uint2*>(dhi)[idx] = hu;
        reinterpret_cast<uint2*>(dlo)[idx] = lu;
    } else {
        const int idx = i - CONV_Q1 - CONV_Q2;             // w2: hi only
        const float4 v = *reinterpret_cast<const float4*>(w2 + (size_t)idx * 4);
        uint2 hu;
        hu.x = pack_h2(v.x, v.y);
        hu.y = pack_h2(v.z, v.w);
        reinterpret_cast<uint2*>(w2h)[idx] = hu;
    }
}

// --------------------------- GEMM1: fp16, 128x128 CTA, 4 warps x 64x64 ------
// C = [xh|xh|xl] @ [wh|wl|wh]' (K'=768), epilogue: +b1, IF sim (+flag),
// write Ah row-major; in-CTA fixup of near-threshold elements.
__global__ __launch_bounds__(128, 2)
void gemm1_f16(const __half* __restrict__ Xh, const __half* __restrict__ Xl,
               const __half* __restrict__ Wh, const __half* __restrict__ Wl,
               const float* __restrict__ bias, __half* __restrict__ Ah,
               const float* __restrict__ xf, const float* __restrict__ w1f)
{
    extern __shared__ __half sm[];                  // 2 * G1_STAGE halves
    __shared__ int s_cnt;
    __shared__ uint32_t s_list[FIX_CAP];
    const uint32_t smb = (uint32_t)__cvta_generic_to_shared(sm);

    const int tid = threadIdx.x;
    const int lane = tid & 31;
    const int wid = tid >> 5;                       // 0..3
    const int g = lane >> 3, lr = lane & 7;
    const int wm = (wid & 1) * 64, wn = (wid >> 1) * 64;   // 2x2 warp grid
    const int mblk = blockIdx.y, nblk = blockIdx.x;

    if (tid == 0) s_cnt = 0;

    int a_off[4], b_off[4];
#pragma unroll
    for (int ma = 0; ma < 4; ma++)
        a_off[ma] = (wm + ma * 16 + (g & 1) * 8 + lr) * STRIDE + (g >> 1) * 8;
#pragma unroll
    for (int nb = 0; nb < 4; nb++)
        b_off[nb] = (128 + wn + nb * 16 + (g >> 1) * 8 + lr) * STRIDE + (g & 1) * 8;

    float acc[4][8][4];                             // 128 fp32 (occ2 @128thr ok)
#pragma unroll
    for (int i = 0; i < 4; i++)
#pragma unroll
        for (int j = 0; j < 8; j++)
#pragma unroll
            for (int k = 0; k < 4; k++) acc[i][j][k] = 0.0f;

    // logical K-tripling: region 0:[xh,wh] 1:[xh,wl] 2:[xl,wh]
    auto load_stage = [&](int s, int kt) {
        const int k0 = kt * 64;
        const int region = k0 >> 8;
        const int koff = k0 & 255;
        const __half* Asrc = (region < 2) ? Xh : Xl;
        const __half* Bsrc = (region == 1) ? Wl : Wh;
#pragma unroll
        for (int i = 0; i < 16; i++) {              // 2048 chunks / 128 thr
            const int c = tid + i * 128;
            const int row = c >> 3, ch = (c & 7) * 8;   // halves
            const __half* gp;
            if (row < 128)
                gp = Asrc + (size_t)(mblk * 128 + row) * IDIM + koff + ch;
            else
                gp = Bsrc + (size_t)(nblk * 128 + (row - 128)) * IDIM + koff + ch;
            cp16(smb + (uint32_t)(s * G1_STAGE + row * STRIDE + ch) * 2, gp);
        }
    };

    load_stage(0, 0);
    CP_COMMIT();
    for (int kt = 0; kt < G1_NK; kt++) {
        CP_WAIT0();
        __syncthreads();        // stage kt visible; prev compute done
        if (kt + 1 < G1_NK) load_stage((kt + 1) & 1, kt + 1);
        CP_COMMIT();            // overlaps the compute below
        const uint32_t stg = smb + (uint32_t)((kt & 1) * G1_STAGE) * 2;
#pragma unroll
        for (int kk = 0; kk < 64; kk += 16) {
            uint32_t a[4][4], b[8][2];
#pragma unroll
            for (int ma = 0; ma < 4; ma++)
                ldm_x4(a[ma], stg + (uint32_t)(a_off[ma] + kk) * 2);
#pragma unroll
            for (int nb = 0; nb < 4; nb++) {
                uint32_t r[4];
                ldm_x4(r, stg + (uint32_t)(b_off[nb] + kk) * 2);
                b[2 * nb][0] = r[0]; b[2 * nb][1] = r[1];
                b[2 * nb + 1][0] = r[2]; b[2 * nb + 1][1] = r[3];
            }
#pragma unroll
            for (int ma = 0; ma < 4; ma++)
#pragma unroll
                for (int na = 0; na < 8; na++) mma_f16(acc[ma][na], a[ma], b[na]);
        }
    }

    // epilogue: +bias, IF sim + flag (smem list), write Ah
    const int gq = lane >> 2, tq = lane & 3;
#pragma unroll
    for (int na = 0; na < 8; na++) {
        const int col = nblk * 128 + wn + na * 8 + 2 * tq;
        const float bb0 = __ldg(bias + col);
        const float bb1 = __ldg(bias + col + 1);
#pragma unroll
        for (int ma = 0; ma < 4; ma++) {
            const int row0 = mblk * 128 + wm + ma * 16 + gq;
#pragma unroll
            for (int rv = 0; rv < 2; rv++) {
                const int row = row0 + rv * 8;
                bool f0 = false, f1 = false;
                const float a0 = if_sim_flag(acc[ma][na][rv * 2 + 0] + bb0, f0);
                const float a1 = if_sim_flag(acc[ma][na][rv * 2 + 1] + bb1, f1);
                const size_t pidx = (size_t)row * (HDIM / 2) + (col >> 1);
                reinterpret_cast<uint32_t*>(Ah)[pidx] = pack_h2(a0, a1);
                if (f0) {
                    const int idx = atomicAdd(&s_cnt, 1);
                    if (idx < FIX_CAP) s_list[idx] = (uint32_t)(row * 1024 + col);
                }
                if (f1) {
                    const int idx = atomicAdd(&s_cnt, 1);
                    if (idx < FIX_CAP) s_list[idx] = (uint32_t)(row * 1024 + col + 1);
                }
            }
        }
    }

    // In-CTA fixup with sequential ascending-k fp32 FMA (reference rounding).
    __syncthreads();
    int n = s_cnt;
    n = n < FIX_CAP ? n : FIX_CAP;
    for (int i = tid; i < n; i += 128) {
        const uint32_t code = s_list[i];
        const int m = code >> 10, j = code & 1023;
        const float* xr = xf + (size_t)m * IDIM;
        const float* wr = w1f + (size_t)j * IDIM;
        float accs = 0.0f;
        for (int k = 0; k < IDIM; k++) accs = fmaf(xr[k], wr[k], accs);
        const float a = if_sim(accs + __ldg(bias + j));
        Ah[(size_t)m * HDIM + j] = __float2half_rn(a);
    }
}

// --------------------------- GEMM2: fp16, 128x64, BK=64 (R10 config) --------
// out = Ah @ wh' (K=1024), + b2*(1-2^-16), fp32 row-major [., 256].
// Stage rows: [0,128) Ah, [128,192) Wh.
__global__ __launch_bounds__(256, 2)
void gemm2_f16(const __half* __restrict__ Ahg, const __half* __restrict__ Wh,
               const float* __restrict__ bias, float* __restrict__ out)
{
    extern __shared__ __half sm[];                  // 2 * G2_STAGE halves
    const uint32_t smb = (uint32_t)__cvta_generic_to_shared(sm);

    const int tid = threadIdx.x;
    const int lane = tid & 31;
    const int wid = tid >> 5;
    const int g = lane >> 3, lr = lane & 7;
    const int wm = (wid & 1) * 64, wn = (wid >> 1) * 16;
    const int mblk = blockIdx.y, nblk = blockIdx.x;

    int a_off[4];
#pragma unroll
    for (int ma = 0; ma < 4; ma++)
        a_off[ma] = (wm + ma * 16 + (g & 1) * 8 + lr) * STRIDE + (g >> 1) * 8;
    const int b_off = (128 + wn + (g >> 1) * 8 + lr) * STRIDE + (g & 1) * 8;

    float acc[4][2][4];
#pragma unroll
    for (int i = 0; i < 4; i++)
#pragma unroll
        for (int j = 0; j < 2; j++)
#pragma unroll
            for (int k = 0; k < 4; k++) acc[i][j][k] = 0.0f;

    auto load_stage = [&](int s, int kt) {
        const int k0 = kt * 64;
#pragma unroll
        for (int i = 0; i < 6; i++) {
            const int c = tid + i * 256;
            const int row = c >> 3, ch = (c & 7) * 8;
            const __half* gp;
            if (row < 128)
                gp = Ahg + (size_t)(mblk * 128 + row) * HDIM + k0 + ch;
            else
                gp = Wh + (size_t)(nblk * 64 + (row - 128)) * HDIM + k0 + ch;
            cp16(smb + (uint32_t)(s * G2_STAGE + row * STRIDE + ch) * 2, gp);
        }
    };

    load_stage(0, 0);
    CP_COMMIT();
    for (int kt = 0; kt < G2_NK; kt++) {
        CP_WAIT0();
        __syncthreads();
        if (kt + 1 < G2_NK) load_stage((kt + 1) & 1, kt + 1);
        CP_COMMIT();
        const uint32_t stg = smb + (uint32_t)((kt & 1) * G2_STAGE) * 2;
#pragma unroll
        for (int kk = 0; kk < 64; kk += 16) {
            uint32_t a[4][4], b[2][2];
#pragma unroll
            for (int ma = 0; ma < 4; ma++)
                ldm_x4(a[ma], stg + (uint32_t)(a_off[ma] + kk) * 2);
            {
                uint32_t r[4];
                ldm_x4(r, stg + (uint32_t)(b_off + kk) * 2);
                b[0][0] = r[0]; b[0][1] = r[1];
                b[1][0] = r[2]; b[1][1] = r[3];
            }
#pragma unroll
            for (int ma = 0; ma < 4; ma++)
#pragma unroll
                for (int na = 0; na < 2; na++) mma_f16(acc[ma][na], a[ma], b[na]);
        }
    }

    const float BSCALE = 1.0f - 0x1p-16f;
    const int gq = lane >> 2, tq = lane & 3;
#pragma unroll
    for (int na = 0; na < 2; na++) {
        const int col = nblk * 64 + wn + na * 8 + 2 * tq;
        const float bb0 = __ldg(bias + col) * BSCALE;
        const float bb1 = __ldg(bias + col + 1) * BSCALE;
#pragma unroll
        for (int ma = 0; ma < 4; ma++) {
            const int row0 = mblk * 128 + wm + ma * 16 + gq;
            *reinterpret_cast<float2*>(out + (size_t)row0 * ODIM + col) =
                make_float2(acc[ma][na][0] + bb0, acc[ma][na][1] + bb1);
            *reinterpret_cast<float2*>(out + (size_t)(row0 + 8) * ODIM + col) =
                make_float2(acc[ma][na][2] + bb0, acc[ma][na][3] + bb1);
        }
    }
}

// --------------------------- launch -----------------------------------------
extern "C" void kernel_launch(void* const* d_in, const int* in_sizes, int n_in,
                              void* d_out, int out_size)
{
    const float* x  = (const float*)d_in[0];   // [8192, 256]
    const float* w1 = (const float*)d_in[1];   // [1024, 256]
    const float* b1 = (const float*)d_in[2];   // [1024]
    const float* w2 = (const float*)d_in[3];   // [256, 1024]
    const float* b2 = (const float*)d_in[4];   // [256]
    float* out = (float*)d_out;                // [8192, 256]

    __half *xh, *xl, *w1h, *w1l, *w2h, *Ah;
    cudaGetSymbolAddress((void**)&xh,  g_xh);
    cudaGetSymbolAddress((void**)&xl,  g_xl);
    cudaGetSymbolAddress((void**)&w1h, g_w1h);
    cudaGetSymbolAddress((void**)&w1l, g_w1l);
    cudaGetSymbolAddress((void**)&w2h, g_w2h);
    cudaGetSymbolAddress((void**)&Ah,  g_Ah);

    cudaFuncSetAttribute(gemm1_f16,
                         cudaFuncAttributeMaxDynamicSharedMemorySize, G1_SMEM);
    cudaFuncSetAttribute(gemm2_f16,
                         cudaFuncAttributeMaxDynamicSharedMemorySize, G2_SMEM);

    conv_all_kernel<<<CONV_QTOTAL / 256, 256>>>(x, w1, w2, xh, xl, w1h, w1l, w2h);

    gemm1_f16<<<dim3(HDIM / 128, MDIM / 128), 128, G1_SMEM>>>(
        xh, xl, w1h, w1l, b1, Ah, x, w1);

    gemm2_f16<<<dim3(ODIM / 64, MDIM / 128), 256, G2_SMEM>>>(
        Ah, w2h, b2, out);
}

// round 15
// speedup vs baseline: 1.4552x; 1.4552x over previous
#include <cuda_runtime.h>
#include <cuda_fp16.h>
#include <cstdint>

// ============================================================================
// DQSN collapsed: out = A @ w2' + b2*(1-2^-16)
//   A[b,j] = sum_t spike_t(h_in[b,j]) * 2^(t-17),  h_in = x@w1' + b1
// GEMM1 (R15): physical-K shared-operand form. Stage holds xh/xl/wh/wl slabs
//   over physical K=256 (BK=32); per k-step computes xh*wh + xh*wl + xl*wh
//   into ONE accumulator, sharing a_xh and b_wh fragments across products:
//   0.25 ldm/mma vs 0.375 for R10's logical tripling (-33% LDS + cp.async).
//   Thread shape is EXACTLY R10's winner: 256 thr, occ 2, 8 warps x 64x32
//   (R12/R14 proved 16 warps/SM is mandatory).
// GEMM2: single-product fp16 Ah @ wh' (K=1024), exact R10 config.
// Near-threshold IF elements (|v-1|<1e-4) recomputed in-CTA with sequential
// fp32 FMA (reference rounding; calibrated R6-R10).
// ============================================================================

#define MDIM 8192
#define IDIM 256
#define HDIM 1024
#define ODIM 256

// ---- GEMM1 geometry: BK=32 over physical K=256 ----
#define G1_NK 8                                // 256 / 32
#define G1_STRIDE 40                           // halves/row (80B, conflict-free)
#define G1_STAGE (512 * G1_STRIDE)             // halves: xh128+xl128+wh128+wl128
#define G1_SMEM (2 * G1_STAGE * 2)             // 81920 B
// ---- GEMM2 geometry: BK=64 over K=1024 (R10) ----
#define G2_NK 16
#define G2_STRIDE 72                           // halves/row (144B)
#define G2_STAGE (192 * G2_STRIDE)             // halves: 128 A + 64 W rows
#define G2_SMEM (2 * G2_STAGE * 2)             // 55296 B

#define FIX_CAP 2048
#define DELTA 1e-4f

// --------------------------- global scratch (no allocs) ---------------------
__device__ __align__(16) __half g_xh [(size_t)MDIM * IDIM];
__device__ __align__(16) __half g_xl [(size_t)MDIM * IDIM];
__device__ __align__(16) __half g_w1h[(size_t)HDIM * IDIM];
__device__ __align__(16) __half g_w1l[(size_t)HDIM * IDIM];
__device__ __align__(16) __half g_w2h[(size_t)ODIM * HDIM];
__device__ __align__(16) __half g_Ah [(size_t)MDIM * HDIM];

// --------------------------- helpers ----------------------------------------
__device__ __forceinline__ void cp16(uint32_t s, const void* g) {
    asm volatile("cp.async.cg.shared.global [%0], [%1], 16;" :: "r"(s), "l"(g));
}
#define CP_COMMIT() asm volatile("cp.async.commit_group;" ::: "memory")
#define CP_WAIT0()  asm volatile("cp.async.wait_group 0;" ::: "memory")

__device__ __forceinline__ void ldm_x4(uint32_t* r, uint32_t addr) {
    asm volatile("ldmatrix.sync.aligned.m8n8.x4.shared.b16 {%0,%1,%2,%3}, [%4];"
        : "=r"(r[0]), "=r"(r[1]), "=r"(r[2]), "=r"(r[3]) : "r"(addr));
}
__device__ __forceinline__ void mma_f16(float* c, const uint32_t* a, const uint32_t* b) {
    asm volatile(
        "mma.sync.aligned.m16n8k16.row.col.f32.f16.f16.f32 "
        "{%0,%1,%2,%3}, {%4,%5,%6,%7}, {%8,%9}, {%0,%1,%2,%3};"
        : "+f"(c[0]), "+f"(c[1]), "+f"(c[2]), "+f"(c[3])
        : "r"(a[0]), "r"(a[1]), "r"(a[2]), "r"(a[3]), "r"(b[0]), "r"(b[1]));
}
__device__ __forceinline__ uint32_t pack_h2(float a, float b) {
    __half2 t = __floats2half2_rn(a, b);
    return *reinterpret_cast<uint32_t*>(&t);
}

// IF neuron closed-form sim
__device__ __forceinline__ float if_sim(float h) {
    float v = 0.0f, av = 0.0f, coef = 0x1p-16f;
#pragma unroll
    for (int t = 0; t < 16; t++) {
        v += h;
        const bool s = (v >= 1.0f);
        av = s ? (av + coef) : av;
        v = s ? 0.0f : v;
        coef += coef;
    }
    return av;
}
__device__ __forceinline__ float if_sim_flag(float h, bool& near) {
    float v = 0.0f, av = 0.0f, coef = 0x1p-16f;
#pragma unroll
    for (int t = 0; t < 16; t++) {
        v += h;
        near |= (fabsf(v - 1.0f) < DELTA);
        const bool s = (v >= 1.0f);
        av = s ? (av + coef) : av;
        v = s ? 0.0f : v;
        coef += coef;
    }
    return av;
}

// --------------------------- fused converter (4 floats/thread) ---------------
#define CONV_Q1 (MDIM * IDIM / 4)
#define CONV_Q2 (HDIM * IDIM / 4)
#define CONV_Q3 (ODIM * HDIM / 4)
#define CONV_QTOTAL (CONV_Q1 + CONV_Q2 + CONV_Q3)

__global__ __launch_bounds__(256)
void conv_all_kernel(const float* __restrict__ x, const float* __restrict__ w1,
                     const float* __restrict__ w2,
                     __half* __restrict__ xh, __half* __restrict__ xl,
                     __half* __restrict__ w1h, __half* __restrict__ w1l,
                     __half* __restrict__ w2h)
{
    const int i = blockIdx.x * blockDim.x + threadIdx.x;   // quad index
    if (i < CONV_Q1 + CONV_Q2) {
        const float* src;
        __half *dhi, *dlo;
        int idx;
        if (i < CONV_Q1) { src = x;  dhi = xh;  dlo = xl;  idx = i; }
        else             { src = w1; dhi = w1h; dlo = w1l; idx = i - CONV_Q1; }
        const float4 v = *reinterpret_cast<const float4*>(src + (size_t)idx * 4);
        const __half h0 = __float2half_rn(v.x), h1 = __float2half_rn(v.y);
        const __half h2 = __float2half_rn(v.z), h3 = __float2half_rn(v.w);
        uint2 hu, lu;
        hu.x = pack_h2(__half2float(h0), __half2float(h1));
        hu.y = pack_h2(__half2float(h2), __half2float(h3));
        lu.x = pack_h2(v.x - __half2float(h0), v.y - __half2float(h1));
        lu.y = pack_h2(v.z - __half2float(h2), v.w - __half2float(h3));
        reinterpret_cast<uint2*>(dhi)[idx] = hu;
        reinterpret_cast<uint2*>(dlo)[idx] = lu;
    } else {
        const int idx = i - CONV_Q1 - CONV_Q2;             // w2: hi only
        const float4 v = *reinterpret_cast<const float4*>(w2 + (size_t)idx * 4);
        uint2 hu;
        hu.x = pack_h2(v.x, v.y);
        hu.y = pack_h2(v.z, v.w);
        reinterpret_cast<uint2*>(w2h)[idx] = hu;
    }
}

// --------------------------- GEMM1: fp16, 128x128 CTA, physical K=256 -------
// Stage rows: [0,128) xh, [128,256) xl, [256,384) wh, [384,512) wl.
// acc += xh*wh + xh*wl + xl*wh per k-step (shared fragments).
// Epilogue: +b1, IF sim (+flag), write Ah; in-CTA fixup.
__global__ __launch_bounds__(256, 2)
void gemm1_f16(const __half* __restrict__ Xh, const __half* __restrict__ Xl,
               const __half* __restrict__ Wh, const __half* __restrict__ Wl,
               const float* __restrict__ bias, __half* __restrict__ Ah,
               const float* __restrict__ xf, const float* __restrict__ w1f)
{
    extern __shared__ __half sm[];                  // 2 * G1_STAGE halves
    __shared__ int s_cnt;
    __shared__ uint32_t s_list[FIX_CAP];
    const uint32_t smb = (uint32_t)__cvta_generic_to_shared(sm);

    const int tid = threadIdx.x;
    const int lane = tid & 31;
    const int wid = tid >> 5;
    const int g = lane >> 3, lr = lane & 7;
    const int wm = (wid & 1) * 64, wn = (wid >> 1) * 32;   // 2x4 warp grid
    const int mblk = blockIdx.y, nblk = blockIdx.x;

    if (tid == 0) s_cnt = 0;

    // ldmatrix row offsets (halves, relative to stage base)
    int axh_off[4], bwh_off[2];
#pragma unroll
    for (int ma = 0; ma < 4; ma++)
        axh_off[ma] = (wm + ma * 16 + (g & 1) * 8 + lr) * G1_STRIDE + (g >> 1) * 8;
#pragma unroll
    for (int nb = 0; nb < 2; nb++)
        bwh_off[nb] = (256 + wn + nb * 16 + (g >> 1) * 8 + lr) * G1_STRIDE + (g & 1) * 8;
    const int XL_OFF = 128 * G1_STRIDE;             // xl rows follow xh
    const int WL_OFF = 128 * G1_STRIDE;             // wl rows follow wh

    float acc[4][4][4];
#pragma unroll
    for (int i = 0; i < 4; i++)
#pragma unroll
        for (int j = 0; j < 4; j++)
#pragma unroll
            for (int k = 0; k < 4; k++) acc[i][j][k] = 0.0f;

    // stage loader: 512 rows x 32 cols fp16 = 2048 16B-chunks, 8 per thread
    auto load_stage = [&](int s, int kt) {
        const int k0 = kt * 32;
#pragma unroll
        for (int i = 0; i < 8; i++) {
            const int c = tid + i * 256;
            const int row = c >> 2, ch = (c & 3) * 8;   // 4 chunks/row
            const __half* gp;
            if (row < 128)
                gp = Xh + (size_t)(mblk * 128 + row) * IDIM + k0 + ch;
            else if (row < 256)
                gp = Xl + (size_t)(mblk * 128 + (row - 128)) * IDIM + k0 + ch;
            else if (row < 384)
                gp = Wh + (size_t)(nblk * 128 + (row - 256)) * IDIM + k0 + ch;
            else
                gp = Wl + (size_t)(nblk * 128 + (row - 384)) * IDIM + k0 + ch;
            cp16(smb + (uint32_t)(s * G1_STAGE + row * G1_STRIDE + ch) * 2, gp);
        }
    };

    load_stage(0, 0);
    CP_COMMIT();
    for (int kt = 0; kt < G1_NK; kt++) {
        CP_WAIT0();
        __syncthreads();        // stage kt visible; prev compute done
        if (kt + 1 < G1_NK) load_stage((kt + 1) & 1, kt + 1);
        CP_COMMIT();            // overlaps the compute below
        const uint32_t stg = smb + (uint32_t)((kt & 1) * G1_STAGE) * 2;
#pragma unroll
        for (int kk = 0; kk < 32; kk += 16) {
            uint32_t a[4][4], bh[4][2], bl[4][2];
            // xh fragments + wh fragments
#pragma unroll
            for (int ma = 0; ma < 4; ma++)
                ldm_x4(a[ma], stg + (uint32_t)(axh_off[ma] + kk) * 2);
#pragma unroll
            for (int nb = 0; nb < 2; nb++) {
                uint32_t r[4];
                ldm_x4(r, stg + (uint32_t)(bwh_off[nb] + kk) * 2);
                bh[2 * nb][0] = r[0]; bh[2 * nb][1] = r[1];
                bh[2 * nb + 1][0] = r[2]; bh[2 * nb + 1][1] = r[3];
            }
            // product 1: xh * wh
#pragma unroll
            for (int ma = 0; ma < 4; ma++)
#pragma unroll
                for (int na = 0; na < 4; na++) mma_f16(acc[ma][na], a[ma], bh[na]);
            // wl fragments; product 2: xh * wl
#pragma unroll
            for (int nb = 0; nb < 2; nb++) {
                uint32_t r[4];
                ldm_x4(r, stg + (uint32_t)(bwh_off[nb] + WL_OFF + kk) * 2);
                bl[2 * nb][0] = r[0]; bl[2 * nb][1] = r[1];
                bl[2 * nb + 1][0] = r[2]; bl[2 * nb + 1][1] = r[3];
            }
#pragma unroll
            for (int ma = 0; ma < 4; ma++)
#pragma unroll
                for (int na = 0; na < 4; na++) mma_f16(acc[ma][na], a[ma], bl[na]);
            // xl fragments (reuse a); product 3: xl * wh
#pragma unroll
            for (int ma = 0; ma < 4; ma++)
                ldm_x4(a[ma], stg + (uint32_t)(axh_off[ma] + XL_OFF + kk) * 2);
#pragma unroll
            for (int ma = 0; ma < 4; ma++)
#pragma unroll
                for (int na = 0; na < 4; na++) mma_f16(acc[ma][na], a[ma], bh[na]);
        }
    }

    // epilogue: +bias, IF sim + flag (smem list), write Ah
    const int gq = lane >> 2, tq = lane & 3;
#pragma unroll
    for (int na = 0; na < 4; na++) {
        const int col = nblk * 128 + wn + na * 8 + 2 * tq;
        const float bb0 = __ldg(bias + col);
        const float bb1 = __ldg(bias + col + 1);
#pragma unroll
        for (int ma = 0; ma < 4; ma++) {
            const int row0 = mblk * 128 + wm + ma * 16 + gq;
#pragma unroll
            for (int rv = 0; rv < 2; rv++) {
                const int row = row0 + rv * 8;
                bool f0 = false, f1 = false;
                const float a0 = if_sim_flag(acc[ma][na][rv * 2 + 0] + bb0, f0);
                const float a1 = if_sim_flag(acc[ma][na][rv * 2 + 1] + bb1, f1);
                const size_t pidx = (size_t)row * (HDIM / 2) + (col >> 1);
                reinterpret_cast<uint32_t*>(Ah)[pidx] = pack_h2(a0, a1);
                if (f0) {
                    const int idx = atomicAdd(&s_cnt, 1);
                    if (idx < FIX_CAP) s_list[idx] = (uint32_t)(row * 1024 + col);
                }
                if (f1) {
                    const int idx = atomicAdd(&s_cnt, 1);
                    if (idx < FIX_CAP) s_list[idx] = (uint32_t)(row * 1024 + col + 1);
                }
            }
        }
    }

    // In-CTA fixup with sequential ascending-k fp32 FMA (reference rounding).
    __syncthreads();
    int n = s_cnt;
    n = n < FIX_CAP ? n : FIX_CAP;
    for (int i = tid; i < n; i += 256) {
        const uint32_t code = s_list[i];
        const int m = code >> 10, j = code & 1023;
        const float* xr = xf + (size_t)m * IDIM;
        const float* wr = w1f + (size_t)j * IDIM;
        float accs = 0.0f;
        for (int k = 0; k < IDIM; k++) accs = fmaf(xr[k], wr[k], accs);
        const float a = if_sim(accs + __ldg(bias + j));
        Ah[(size_t)m * HDIM + j] = __float2half_rn(a);
    }
}

// --------------------------- GEMM2: fp16, 128x64, BK=64 (R10 config) --------
// out = Ah @ wh' (K=1024), + b2*(1-2^-16), fp32 row-major [., 256].
// Stage rows: [0,128) Ah, [128,192) Wh.
__global__ __launch_bounds__(256, 2)
void gemm2_f16(const __half* __restrict__ Ahg, const __half* __restrict__ Wh,
               const float* __restrict__ bias, float* __restrict__ out)
{
    extern __shared__ __half sm[];                  // 2 * G2_STAGE halves
    const uint32_t smb = (uint32_t)__cvta_generic_to_shared(sm);

    const int tid = threadIdx.x;
    const int lane = tid & 31;
    const int wid = tid >> 5;
    const int g = lane >> 3, lr = lane & 7;
    const int wm = (wid & 1) * 64, wn = (wid >> 1) * 16;
    const int mblk = blockIdx.y, nblk = blockIdx.x;

    int a_off[4];
#pragma unroll
    for (int ma = 0; ma < 4; ma++)
        a_off[ma] = (wm + ma * 16 + (g & 1) * 8 + lr) * G2_STRIDE + (g >> 1) * 8;
    const int b_off = (128 + wn + (g >> 1) * 8 + lr) * G2_STRIDE + (g & 1) * 8;

    float acc[4][2][4];
#pragma unroll
    for (int i = 0; i < 4; i++)
#pragma unroll
        for (int j = 0; j < 2; j++)
#pragma unroll
            for (int k = 0; k < 4; k++) acc[i][j][k] = 0.0f;

    auto load_stage = [&](int s, int kt) {
        const int k0 = kt * 64;
#pragma unroll
        for (int i = 0; i < 6; i++) {
            const int c = tid + i * 256;
            const int row = c >> 3, ch = (c & 7) * 8;
            const __half* gp;
            if (row < 128)
                gp = Ahg + (size_t)(mblk * 128 + row) * HDIM + k0 + ch;
            else
                gp = Wh + (size_t)(nblk * 64 + (row - 128)) * HDIM + k0 + ch;
            cp16(smb + (uint32_t)(s * G2_STAGE + row * G2_STRIDE + ch) * 2, gp);
        }
    };

    load_stage(0, 0);
    CP_COMMIT();
    for (int kt = 0; kt < G2_NK; kt++) {
        CP_WAIT0();
        __syncthreads();
        if (kt + 1 < G2_NK) load_stage((kt + 1) & 1, kt + 1);
        CP_COMMIT();
        const uint32_t stg = smb + (uint32_t)((kt & 1) * G2_STAGE) * 2;
#pragma unroll
        for (int kk = 0; kk < 64; kk += 16) {
            uint32_t a[4][4], b[2][2];
#pragma unroll
            for (int ma = 0; ma < 4; ma++)
                ldm_x4(a[ma], stg + (uint32_t)(a_off[ma] + kk) * 2);
            {
                uint32_t r[4];
                ldm_x4(r, stg + (uint32_t)(b_off + kk) * 2);
                b[0][0] = r[0]; b[0][1] = r[1];
                b[1][0] = r[2]; b[1][1] = r[3];
            }
#pragma unroll
            for (int ma = 0; ma < 4; ma++)
#pragma unroll
                for (int na = 0; na < 2; na++) mma_f16(acc[ma][na], a[ma], b[na]);
        }
    }

    const float BSCALE = 1.0f - 0x1p-16f;
    const int gq = lane >> 2, tq = lane & 3;
#pragma unroll
    for (int na = 0; na < 2; na++) {
        const int col = nblk * 64 + wn + na * 8 + 2 * tq;
        const float bb0 = __ldg(bias + col) * BSCALE;
        const float bb1 = __ldg(bias + col + 1) * BSCALE;
#pragma unroll
        for (int ma = 0; ma < 4; ma++) {
            const int row0 = mblk * 128 + wm + ma * 16 + gq;
            *reinterpret_cast<float2*>(out + (size_t)row0 * ODIM + col) =
                make_float2(acc[ma][na][0] + bb0, acc[ma][na][1] + bb1);
            *reinterpret_cast<float2*>(out + (size_t)(row0 + 8) * ODIM + col) =
                make_float2(acc[ma][na][2] + bb0, acc[ma][na][3] + bb1);
        }
    }
}

// --------------------------- launch -----------------------------------------
extern "C" void kernel_launch(void* const* d_in, const int* in_sizes, int n_in,
                              void* d_out, int out_size)
{
    const float* x  = (const float*)d_in[0];   // [8192, 256]
    const float* w1 = (const float*)d_in[1];   // [1024, 256]
    const float* b1 = (const float*)d_in[2];   // [1024]
    const float* w2 = (const float*)d_in[3];   // [256, 1024]
    const float* b2 = (const float*)d_in[4];   // [256]
    float* out = (float*)d_out;                // [8192, 256]

    __half *xh, *xl, *w1h, *w1l, *w2h, *Ah;
    cudaGetSymbolAddress((void**)&xh,  g_xh);
    cudaGetSymbolAddress((void**)&xl,  g_xl);
    cudaGetSymbolAddress((void**)&w1h, g_w1h);
    cudaGetSymbolAddress((void**)&w1l, g_w1l);
    cudaGetSymbolAddress((void**)&w2h, g_w2h);
    cudaGetSymbolAddress((void**)&Ah,  g_Ah);

    cudaFuncSetAttribute(gemm1_f16,
                         cudaFuncAttributeMaxDynamicSharedMemorySize, G1_SMEM);
    cudaFuncSetAttribute(gemm2_f16,
                         cudaFuncAttributeMaxDynamicSharedMemorySize, G2_SMEM);

    conv_all_kernel<<<CONV_QTOTAL / 256, 256>>>(x, w1, w2, xh, xl, w1h, w1l, w2h);

    gemm1_f16<<<dim3(HDIM / 128, MDIM / 128), 256, G1_SMEM>>>(
        xh, xl, w1h, w1l, b1, Ah, x, w1);

    gemm2_f16<<<dim3(ODIM / 64, MDIM / 128), 256, G2_SMEM>>>(
        Ah, w2h, b2, out);
}

// round 16
// speedup vs baseline: 1.4707x; 1.0106x over previous
#include <cuda_runtime.h>
#include <cuda_fp16.h>
#include <cstdint>

// ============================================================================
// DQSN collapsed: out = A @ w2' + b2*(1-2^-16)
//   A[b,j] = sum_t spike_t(h_in[b,j]) * 2^(t-17),  h_in = x@w1' + b1
// GEMM1 (R15 winner, unchanged): physical-K shared-operand form, BK=32 over
//   K=256; per k-step xh*wh + xh*wl + xl*wh into one accumulator.
//   256 thr, occ 2, 8 warps x 64x32 (16 warps/SM mandatory: R12/R14).
// GEMM2 (R16): 32x32 warp tiles (0.5 ldm/mma vs 0.625) + 3-stage cp.async
//   pipeline (wait_group 1, slot = kt%3). R15 showed gemm2 at ~67 TMAC/s vs
//   gemm1's ~95 -- it is the LDS-ratio-bound kernel now.
// Near-threshold IF elements (|v-1|<1e-4) recomputed in-CTA with sequential
// fp32 FMA (reference rounding; calibrated R6-R10).
// ============================================================================

#define MDIM 8192
#define IDIM 256
#define HDIM 1024
#define ODIM 256

// ---- GEMM1 geometry: BK=32 over physical K=256 ----
#define G1_NK 8                                // 256 / 32
#define G1_STRIDE 40                           // halves/row (80B, conflict-free)
#define G1_STAGE (512 * G1_STRIDE)             // halves: xh128+xl128+wh128+wl128
#define G1_SMEM (2 * G1_STAGE * 2)             // 81920 B
// ---- GEMM2 geometry: BK=64 over K=1024, 3 stages ----
#define G2_NK 16
#define G2_STRIDE 72                           // halves/row (144B)
#define G2_STAGE (192 * G2_STRIDE)             // halves: 128 A + 64 W rows
#define G2_SMEM (3 * G2_STAGE * 2)             // 82944 B (x2 CTAs = 166KB ok)

#define FIX_CAP 2048
#define DELTA 1e-4f

// --------------------------- global scratch (no allocs) ---------------------
__device__ __align__(16) __half g_xh [(size_t)MDIM * IDIM];
__device__ __align__(16) __half g_xl [(size_t)MDIM * IDIM];
__device__ __align__(16) __half g_w1h[(size_t)HDIM * IDIM];
__device__ __align__(16) __half g_w1l[(size_t)HDIM * IDIM];
__device__ __align__(16) __half g_w2h[(size_t)ODIM * HDIM];
__device__ __align__(16) __half g_Ah [(size_t)MDIM * HDIM];

// --------------------------- helpers ----------------------------------------
__device__ __forceinline__ void cp16(uint32_t s, const void* g) {
    asm volatile("cp.async.cg.shared.global [%0], [%1], 16;" :: "r"(s), "l"(g));
}
#define CP_COMMIT() asm volatile("cp.async.commit_group;" ::: "memory")
#define CP_WAIT0()  asm volatile("cp.async.wait_group 0;" ::: "memory")
#define CP_WAIT1()  asm volatile("cp.async.wait_group 1;" ::: "memory")

__device__ __forceinline__ void ldm_x4(uint32_t* r, uint32_t addr) {
    asm volatile("ldmatrix.sync.aligned.m8n8.x4.shared.b16 {%0,%1,%2,%3}, [%4];"
        : "=r"(r[0]), "=r"(r[1]), "=r"(r[2]), "=r"(r[3]) : "r"(addr));
}
__device__ __forceinline__ void mma_f16(float* c, const uint32_t* a, const uint32_t* b) {
    asm volatile(
        "mma.sync.aligned.m16n8k16.row.col.f32.f16.f16.f32 "
        "{%0,%1,%2,%3}, {%4,%5,%6,%7}, {%8,%9}, {%0,%1,%2,%3};"
        : "+f"(c[0]), "+f"(c[1]), "+f"(c[2]), "+f"(c[3])
        : "r"(a[0]), "r"(a[1]), "r"(a[2]), "r"(a[3]), "r"(b[0]), "r"(b[1]));
}
__device__ __forceinline__ uint32_t pack_h2(float a, float b) {
    __half2 t = __floats2half2_rn(a, b);
    return *reinterpret_cast<uint32_t*>(&t);
}

// IF neuron closed-form sim
__device__ __forceinline__ float if_sim(float h) {
    float v = 0.0f, av = 0.0f, coef = 0x1p-16f;
#pragma unroll
    for (int t = 0; t < 16; t++) {
        v += h;
        const bool s = (v >= 1.0f);
        av = s ? (av + coef) : av;
        v = s ? 0.0f : v;
        coef += coef;
    }
    return av;
}
__device__ __forceinline__ float if_sim_flag(float h, bool& near) {
    float v = 0.0f, av = 0.0f, coef = 0x1p-16f;
#pragma unroll
    for (int t = 0; t < 16; t++) {
        v += h;
        near |= (fabsf(v - 1.0f) < DELTA);
        const bool s = (v >= 1.0f);
        av = s ? (av + coef) : av;
        v = s ? 0.0f : v;
        coef += coef;
    }
    return av;
}

// --------------------------- fused converter (4 floats/thread) ---------------
#define CONV_Q1 (MDIM * IDIM / 4)
#define CONV_Q2 (HDIM * IDIM / 4)
#define CONV_Q3 (ODIM * HDIM / 4)
#define CONV_QTOTAL (CONV_Q1 + CONV_Q2 + CONV_Q3)

__global__ __launch_bounds__(256)
void conv_all_kernel(const float* __restrict__ x, const float* __restrict__ w1,
                     const float* __restrict__ w2,
                     __half* __restrict__ xh, __half* __restrict__ xl,
                     __half* __restrict__ w1h, __half* __restrict__ w1l,
                     __half* __restrict__ w2h)
{
    const int i = blockIdx.x * blockDim.x + threadIdx.x;   // quad index
    if (i < CONV_Q1 + CONV_Q2) {
        const float* src;
        __half *dhi, *dlo;
        int idx;
        if (i < CONV_Q1) { src = x;  dhi = xh;  dlo = xl;  idx = i; }
        else             { src = w1; dhi = w1h; dlo = w1l; idx = i - CONV_Q1; }
        const float4 v = *reinterpret_cast<const float4*>(src + (size_t)idx * 4);
        const __half h0 = __float2half_rn(v.x), h1 = __float2half_rn(v.y);
        const __half h2 = __float2half_rn(v.z), h3 = __float2half_rn(v.w);
        uint2 hu, lu;
        hu.x = pack_h2(__half2float(h0), __half2float(h1));
        hu.y = pack_h2(__half2float(h2), __half2float(h3));
        lu.x = pack_h2(v.x - __half2float(h0), v.y - __half2float(h1));
        lu.y = pack_h2(v.z - __half2float(h2), v.w - __half2float(h3));
        reinterpret_cast<uint2*>(dhi)[idx] = hu;
        reinterpret_cast<uint2*>(dlo)[idx] = lu;
    } else {
        const int idx = i - CONV_Q1 - CONV_Q2;             // w2: hi only
        const float4 v = *reinterpret_cast<const float4*>(w2 + (size_t)idx * 4);
        uint2 hu;
        hu.x = pack_h2(v.x, v.y);
        hu.y = pack_h2(v.z, v.w);
        reinterpret_cast<uint2*>(w2h)[idx] = hu;
    }
}

// --------------------------- GEMM1: fp16, 128x128 CTA, physical K=256 -------
// Stage rows: [0,128) xh, [128,256) xl, [256,384) wh, [384,512) wl.
// acc += xh*wh + xh*wl + xl*wh per k-step (shared fragments).
// Epilogue: +b1, IF sim (+flag), write Ah; in-CTA fixup.
__global__ __launch_bounds__(256, 2)
void gemm1_f16(const __half* __restrict__ Xh, const __half* __restrict__ Xl,
               const __half* __restrict__ Wh, const __half* __restrict__ Wl,
               const float* __restrict__ bias, __half* __restrict__ Ah,
               const float* __restrict__ xf, const float* __restrict__ w1f)
{
    extern __shared__ __half sm[];                  // 2 * G1_STAGE halves
    __shared__ int s_cnt;
    __shared__ uint32_t s_list[FIX_CAP];
    const uint32_t smb = (uint32_t)__cvta_generic_to_shared(sm);

    const int tid = threadIdx.x;
    const int lane = tid & 31;
    const int wid = tid >> 5;
    const int g = lane >> 3, lr = lane & 7;
    const int wm = (wid & 1) * 64, wn = (wid >> 1) * 32;   // 2x4 warp grid
    const int mblk = blockIdx.y, nblk = blockIdx.x;

    if (tid == 0) s_cnt = 0;

    int axh_off[4], bwh_off[2];
#pragma unroll
    for (int ma = 0; ma < 4; ma++)
        axh_off[ma] = (wm + ma * 16 + (g & 1) * 8 + lr) * G1_STRIDE + (g >> 1) * 8;
#pragma unroll
    for (int nb = 0; nb < 2; nb++)
        bwh_off[nb] = (256 + wn + nb * 16 + (g >> 1) * 8 + lr) * G1_STRIDE + (g & 1) * 8;
    const int XL_OFF = 128 * G1_STRIDE;
    const int WL_OFF = 128 * G1_STRIDE;

    float acc[4][4][4];
#pragma unroll
    for (int i = 0; i < 4; i++)
#pragma unroll
        for (int j = 0; j < 4; j++)
#pragma unroll
            for (int k = 0; k < 4; k++) acc[i][j][k] = 0.0f;

    auto load_stage = [&](int s, int kt) {
        const int k0 = kt * 32;
#pragma unroll
        for (int i = 0; i < 8; i++) {
            const int c = tid + i * 256;
            const int row = c >> 2, ch = (c & 3) * 8;
            const __half* gp;
            if (row < 128)
                gp = Xh + (size_t)(mblk * 128 + row) * IDIM + k0 + ch;
            else if (row < 256)
                gp = Xl + (size_t)(mblk * 128 + (row - 128)) * IDIM + k0 + ch;
            else if (row < 384)
                gp = Wh + (size_t)(nblk * 128 + (row - 256)) * IDIM + k0 + ch;
            else
                gp = Wl + (size_t)(nblk * 128 + (row - 384)) * IDIM + k0 + ch;
            cp16(smb + (uint32_t)(s * G1_STAGE + row * G1_STRIDE + ch) * 2, gp);
        }
    };

    load_stage(0, 0);
    CP_COMMIT();
    for (int kt = 0; kt < G1_NK; kt++) {
        CP_WAIT0();
        __syncthreads();
        if (kt + 1 < G1_NK) load_stage((kt + 1) & 1, kt + 1);
        CP_COMMIT();
        const uint32_t stg = smb + (uint32_t)((kt & 1) * G1_STAGE) * 2;
#pragma unroll
        for (int kk = 0; kk < 32; kk += 16) {
            uint32_t a[4][4], bh[4][2], bl[4][2];
#pragma unroll
            for (int ma = 0; ma < 4; ma++)
                ldm_x4(a[ma], stg + (uint32_t)(axh_off[ma] + kk) * 2);
#pragma unroll
            for (int nb = 0; nb < 2; nb++) {
                uint32_t r[4];
                ldm_x4(r, stg + (uint32_t)(bwh_off[nb] + kk) * 2);
                bh[2 * nb][0] = r[0]; bh[2 * nb][1] = r[1];
                bh[2 * nb + 1][0] = r[2]; bh[2 * nb + 1][1] = r[3];
            }
#pragma unroll
            for (int ma = 0; ma < 4; ma++)
#pragma unroll
                for (int na = 0; na < 4; na++) mma_f16(acc[ma][na], a[ma], bh[na]);
#pragma unroll
            for (int nb = 0; nb < 2; nb++) {
                uint32_t r[4];
                ldm_x4(r, stg + (uint32_t)(bwh_off[nb] + WL_OFF + kk) * 2);
                bl[2 * nb][0] = r[0]; bl[2 * nb][1] = r[1];
                bl[2 * nb + 1][0] = r[2]; bl[2 * nb + 1][1] = r[3];
            }
#pragma unroll
            for (int ma = 0; ma < 4; ma++)
#pragma unroll
                for (int na = 0; na < 4; na++) mma_f16(acc[ma][na], a[ma], bl[na]);
#pragma unroll
            for (int ma = 0; ma < 4; ma++)
                ldm_x4(a[ma], stg + (uint32_t)(axh_off[ma] + XL_OFF + kk) * 2);
#pragma unroll
            for (int ma = 0; ma < 4; ma++)
#pragma unroll
                for (int na = 0; na < 4; na++) mma_f16(acc[ma][na], a[ma], bh[na]);
        }
    }

    // epilogue: +bias, IF sim + flag (smem list), write Ah
    const int gq = lane >> 2, tq = lane & 3;
#pragma unroll
    for (int na = 0; na < 4; na++) {
        const int col = nblk * 128 + wn + na * 8 + 2 * tq;
        const float bb0 = __ldg(bias + col);
        const float bb1 = __ldg(bias + col + 1);
#pragma unroll
        for (int ma = 0; ma < 4; ma++) {
            const int row0 = mblk * 128 + wm + ma * 16 + gq;
#pragma unroll
            for (int rv = 0; rv < 2; rv++) {
                const int row = row0 + rv * 8;
                bool f0 = false, f1 = false;
                const float a0 = if_sim_flag(acc[ma][na][rv * 2 + 0] + bb0, f0);
                const float a1 = if_sim_flag(acc[ma][na][rv * 2 + 1] + bb1, f1);
                const size_t pidx = (size_t)row * (HDIM / 2) + (col >> 1);
                reinterpret_cast<uint32_t*>(Ah)[pidx] = pack_h2(a0, a1);
                if (f0) {
                    const int idx = atomicAdd(&s_cnt, 1);
                    if (idx < FIX_CAP) s_list[idx] = (uint32_t)(row * 1024 + col);
                }
                if (f1) {
                    const int idx = atomicAdd(&s_cnt, 1);
                    if (idx < FIX_CAP) s_list[idx] = (uint32_t)(row * 1024 + col + 1);
                }
            }
        }
    }

    // In-CTA fixup with sequential ascending-k fp32 FMA (reference rounding).
    __syncthreads();
    int n = s_cnt;
    n = n < FIX_CAP ? n : FIX_CAP;
    for (int i = tid; i < n; i += 256) {
        const uint32_t code = s_list[i];
        const int m = code >> 10, j = code & 1023;
        const float* xr = xf + (size_t)m * IDIM;
        const float* wr = w1f + (size_t)j * IDIM;
        float accs = 0.0f;
        for (int k = 0; k < IDIM; k++) accs = fmaf(xr[k], wr[k], accs);
        const float a = if_sim(accs + __ldg(bias + j));
        Ah[(size_t)m * HDIM + j] = __float2half_rn(a);
    }
}

// --------------------------- GEMM2: fp16, 128x64, BK=64, 3-stage, 32x32 -----
// out = Ah @ wh' (K=1024), + b2*(1-2^-16), fp32 row-major [., 256].
// Stage rows: [0,128) Ah, [128,192) Wh. Warp grid 4x2, warp tile 32x32.
__global__ __launch_bounds__(256, 2)
void gemm2_f16(const __half* __restrict__ Ahg, const __half* __restrict__ Wh,
               const float* __restrict__ bias, float* __restrict__ out)
{
    extern __shared__ __half sm[];                  // 3 * G2_STAGE halves
    const uint32_t smb = (uint32_t)__cvta_generic_to_shared(sm);

    const int tid = threadIdx.x;
    const int lane = tid & 31;
    const int wid = tid >> 5;
    const int g = lane >> 3, lr = lane & 7;
    const int wm = (wid & 3) * 32, wn = (wid >> 2) * 32;   // 4x2 warp grid
    const int mblk = blockIdx.y, nblk = blockIdx.x;

    int a_off[2], b_off[2];
#pragma unroll
    for (int ma = 0; ma < 2; ma++)
        a_off[ma] = (wm + ma * 16 + (g & 1) * 8 + lr) * G2_STRIDE + (g >> 1) * 8;
#pragma unroll
    for (int nb = 0; nb < 2; nb++)
        b_off[nb] = (128 + wn + nb * 16 + (g >> 1) * 8 + lr) * G2_STRIDE + (g & 1) * 8;

    float acc[2][4][4];
#pragma unroll
    for (int i = 0; i < 2; i++)
#pragma unroll
        for (int j = 0; j < 4; j++)
#pragma unroll
            for (int k = 0; k < 4; k++) acc[i][j][k] = 0.0f;

    auto load_stage = [&](int s, int kt) {
        const int k0 = kt * 64;
#pragma unroll
        for (int i = 0; i < 6; i++) {
            const int c = tid + i * 256;
            const int row = c >> 3, ch = (c & 7) * 8;
            const __half* gp;
            if (row < 128)
                gp = Ahg + (size_t)(mblk * 128 + row) * HDIM + k0 + ch;
            else
                gp = Wh + (size_t)(nblk * 64 + (row - 128)) * HDIM + k0 + ch;
            cp16(smb + (uint32_t)(s * G2_STAGE + row * G2_STRIDE + ch) * 2, gp);
        }
    };

    load_stage(0, 0); CP_COMMIT();
    load_stage(1, 1); CP_COMMIT();
    for (int kt = 0; kt < G2_NK; kt++) {
        CP_WAIT1();             // tile kt complete (kt+1 may be in flight)
        __syncthreads();
        if (kt + 2 < G2_NK) load_stage((kt + 2) % 3, kt + 2);
        CP_COMMIT();            // overlaps compute below (2-tile slack)
        const uint32_t stg = smb + (uint32_t)((kt % 3) * G2_STAGE) * 2;
#pragma unroll
        for (int kk = 0; kk < 64; kk += 16) {
            uint32_t a[2][4], b[4][2];
#pragma unroll
            for (int ma = 0; ma < 2; ma++)
                ldm_x4(a[ma], stg + (uint32_t)(a_off[ma] + kk) * 2);
#pragma unroll
            for (int nb = 0; nb < 2; nb++) {
                uint32_t r[4];
                ldm_x4(r, stg + (uint32_t)(b_off[nb] + kk) * 2);
                b[2 * nb][0] = r[0]; b[2 * nb][1] = r[1];
                b[2 * nb + 1][0] = r[2]; b[2 * nb + 1][1] = r[3];
            }
#pragma unroll
            for (int ma = 0; ma < 2; ma++)
#pragma unroll
                for (int na = 0; na < 4; na++) mma_f16(acc[ma][na], a[ma], b[na]);
        }
    }

    const float BSCALE = 1.0f - 0x1p-16f;
    const int gq = lane >> 2, tq = lane & 3;
#pragma unroll
    for (int na = 0; na < 4; na++) {
        const int col = nblk * 64 + wn + na * 8 + 2 * tq;
        const float bb0 = __ldg(bias + col) * BSCALE;
        const float bb1 = __ldg(bias + col + 1) * BSCALE;
#pragma unroll
        for (int ma = 0; ma < 2; ma++) {
            const int row0 = mblk * 128 + wm + ma * 16 + gq;
            *reinterpret_cast<float2*>(out + (size_t)row0 * ODIM + col) =
                make_float2(acc[ma][na][0] + bb0, acc[ma][na][1] + bb1);
            *reinterpret_cast<float2*>(out + (size_t)(row0 + 8) * ODIM + col) =
                make_float2(acc[ma][na][2] + bb0, acc[ma][na][3] + bb1);
        }
    }
}

// --------------------------- launch -----------------------------------------
extern "C" void kernel_launch(void* const* d_in, const int* in_sizes, int n_in,
                              void* d_out, int out_size)
{
    const float* x  = (const float*)d_in[0];   // [8192, 256]
    const float* w1 = (const float*)d_in[1];   // [1024, 256]
    const float* b1 = (const float*)d_in[2];   // [1024]
    const float* w2 = (const float*)d_in[3];   // [256, 1024]
    const float* b2 = (const float*)d_in[4];   // [256]
    float* out = (float*)d_out;                // [8192, 256]

    __half *xh, *xl, *w1h, *w1l, *w2h, *Ah;
    cudaGetSymbolAddress((void**)&xh,  g_xh);
    cudaGetSymbolAddress((void**)&xl,  g_xl);
    cudaGetSymbolAddress((void**)&w1h, g_w1h);
    cudaGetSymbolAddress((void**)&w1l, g_w1l);
    cudaGetSymbolAddress((void**)&w2h, g_w2h);
    cudaGetSymbolAddress((void**)&Ah,  g_Ah);

    cudaFuncSetAttribute(gemm1_f16,
                         cudaFuncAttributeMaxDynamicSharedMemorySize, G1_SMEM);
    cudaFuncSetAttribute(gemm2_f16,
                         cudaFuncAttributeMaxDynamicSharedMemorySize, G2_SMEM);

    conv_all_kernel<<<CONV_QTOTAL / 256, 256>>>(x, w1, w2, xh, xl, w1h, w1l, w2h);

    gemm1_f16<<<dim3(HDIM / 128, MDIM / 128), 256, G1_SMEM>>>(
        xh, xl, w1h, w1l, b1, Ah, x, w1);

    gemm2_f16<<<dim3(ODIM / 64, MDIM / 128), 256, G2_SMEM>>>(
        Ah, w2h, b2, out);
}